// round 6
// baseline (speedup 1.0000x reference)
#include <cuda_runtime.h>
#include <cuda_bf16.h>
#include <cstdint>

#define BATCH 2048
#define NCLS  1000
#define DIM   128
#define TM 64
#define TN 128
#define ROWB 272            // bf16 tile row stride: 256B + 16B pad
#define NCTA 256
#define STW 132             // f32 staging tile row stride (floats): 528B

// deterministic likelihood partials (one per CTA) + completion ticket
__device__ __align__(16) float g_part[NCTA];
__device__ int g_ticket;

// ---- smem byte offsets ----
#define OFF_A   0                       // A bf16 tile: 64 x 272B  = 17408
#define OFF_B   17408                   // B bf16 tile: 128 x 272B = 34816
#define OFF_ST  0                       // f32 dot staging 64 x 528B = 33792 (aliases A+B)
#define OFF_FNP 52224                   // float[64][4]  feat norm partials
#define OFF_CNP 53248                   // float[128][2] center norm partials
#define OFF_FNC 54272                   // float[64]   0.5*||f||^2
#define OFF_CNC 54528                   // float[128]  0.5*||c||^2
#define OFF_RED 55040                   // float[8] warp partials
#define SMEM_BYTES 55104

static __device__ __forceinline__ uint32_t smem_u32(const void* p) {
    uint32_t a;
    asm("{ .reg .u64 t; cvta.to.shared.u64 t, %1; cvt.u32.u64 %0, t; }"
        : "=r"(a) : "l"(p));
    return a;
}

static __device__ __forceinline__ int get_label(const void* lab, int b, int is64) {
    if (is64) return (int)(((const long long*)lab)[b]);
    return ((const int*)lab)[b];
}

static __device__ __forceinline__ uint32_t bf2(float x, float y) {
    __nv_bfloat162 v = __floats2bfloat162_rn(x, y);
    return *(uint32_t*)&v;
}

#define LDSM_X4(d, addr)                                                        \
    asm volatile("ldmatrix.sync.aligned.m8n8.x4.shared.b16 {%0,%1,%2,%3},[%4];" \
        : "=r"((d)[0]), "=r"((d)[1]), "=r"((d)[2]), "=r"((d)[3])                \
        : "r"(addr))

#define MMA16816(d, a, b0, b1)                                                  \
    asm volatile("mma.sync.aligned.m16n8k16.row.col.f32.bf16.bf16.f32 "         \
        "{%0,%1,%2,%3}, {%4,%5,%6,%7}, {%8,%9}, {%0,%1,%2,%3};"                 \
        : "+f"((d)[0]), "+f"((d)[1]), "+f"((d)[2]), "+f"((d)[3])                \
        : "r"((a)[0]), "r"((a)[1]), "r"((a)[2]), "r"((a)[3]),                   \
          "r"(b0), "r"(b1))

__global__ void __launch_bounds__(256, 2)
lgm_mma_kernel(const float* __restrict__ feat,
               const void*  __restrict__ label,
               const float* __restrict__ centers,
               float* __restrict__ logits,
               float* __restrict__ mlogits,
               float* __restrict__ lik)
{
    extern __shared__ char smem[];
    const uint32_t sb = smem_u32(smem);
    const int tid = threadIdx.x;
    const int bb = blockIdx.y * TM;      // feat-row base
    const int cc = blockIdx.x * TN;      // center-col base

    // ---------------- staging: f32 -> bf16 tiles + fused norms ----------------
    {   // A = feat: 64 rows x 128 cols; thread -> (row, 32-col quarter)
        // FULL quarter: 8 LDG.128 (32 floats) -> 4 STS.128 (32 bf16)
        const int r = tid & 63;
        const int q = tid >> 6;
        const float4* src = (const float4*)(feat + (size_t)(bb + r) * DIM + q * 32);
        float4 v[8];
#pragma unroll
        for (int j = 0; j < 8; j++) v[j] = src[j];
        float s = 0.f;
        char* dst = smem + OFF_A + r * ROWB + q * 64;
#pragma unroll
        for (int j = 0; j < 4; j++) {
            float4 a = v[2 * j], b = v[2 * j + 1];
            s += a.x*a.x + a.y*a.y + a.z*a.z + a.w*a.w
               + b.x*b.x + b.y*b.y + b.z*b.z + b.w*b.w;
            uint4 p;
            p.x = bf2(a.x, a.y); p.y = bf2(a.z, a.w);
            p.z = bf2(b.x, b.y); p.w = bf2(b.z, b.w);
            *(uint4*)(dst + j * 16) = p;
        }
        ((float*)(smem + OFF_FNP))[r * 4 + q] = s;
    }
    {   // B = centers: 128 rows x 128 cols; thread -> (row, 64-col half)
        // FULL half: 16 LDG.128 (64 floats) -> 8 STS.128 (64 bf16)
        const int r = tid & 127;
        const int h = tid >> 7;
        const int crow = cc + r;
        const bool ok = crow < NCLS;
        const float4* src = (const float4*)(centers + (size_t)crow * DIM + h * 64);
        float4 v[16];
#pragma unroll
        for (int j = 0; j < 16; j++)
            v[j] = ok ? src[j] : make_float4(0.f, 0.f, 0.f, 0.f);
        float s = 0.f;
        char* dst = smem + OFF_B + r * ROWB + h * 128;
#pragma unroll
        for (int j = 0; j < 8; j++) {
            float4 a = v[2 * j], b = v[2 * j + 1];
            s += a.x*a.x + a.y*a.y + a.z*a.z + a.w*a.w
               + b.x*b.x + b.y*b.y + b.z*b.z + b.w*b.w;
            uint4 p;
            p.x = bf2(a.x, a.y); p.y = bf2(a.z, a.w);
            p.z = bf2(b.x, b.y); p.w = bf2(b.z, b.w);
            *(uint4*)(dst + j * 16) = p;
        }
        ((float*)(smem + OFF_CNP))[r * 2 + h] = s;
    }

    // label dtype probe (global rows 0..127, in-bounds for both widths)
    int hw = 0;
    if (tid < 128) hw = (((const int*)label)[2 * tid + 1] != 0);
    const int is64 = !__syncthreads_or(hw);   // barrier also covers tile stores

    if (tid < 64) {
        const float* fnp = (const float*)(smem + OFF_FNP) + tid * 4;
        ((float*)(smem + OFF_FNC))[tid] =
            0.5f * ((fnp[0] + fnp[1]) + (fnp[2] + fnp[3]));
    }
    if (tid < 128) {
        const float* cnp = (const float*)(smem + OFF_CNP);
        ((float*)(smem + OFF_CNC))[tid] = 0.5f * (cnp[2 * tid] + cnp[2 * tid + 1]);
    }
    __syncthreads();

    // ---------------- HMMA mainloop: warp = 32(M) x 32(N) ----------------
    const int wid  = tid >> 5;
    const int lane = tid & 31;
    const int wm = wid & 1;          // rows wm*32..+31
    const int wn = wid >> 1;         // cols wn*32..+31

    const uint32_t la  = sb + OFF_A + (wm * 32 + (lane & 15)) * ROWB + (lane >> 4) * 16;
    const uint32_t lbm = sb + OFF_B + (wn * 32 + (lane & 15)) * ROWB + (lane >> 4) * 16;

    float acc[2][4][4] = {};
#pragma unroll
    for (int ks = 0; ks < 8; ks++) {
        const uint32_t ko = ks * 32;
        uint32_t a[2][4], b[2][4];
        LDSM_X4(a[0], la + ko);
        LDSM_X4(a[1], la + 16 * ROWB + ko);
        LDSM_X4(b[0], lbm + ko);
        LDSM_X4(b[1], lbm + 16 * ROWB + ko);
#pragma unroll
        for (int mi = 0; mi < 2; mi++)
#pragma unroll
            for (int nb = 0; nb < 2; nb++) {
                MMA16816(acc[mi][nb * 2 + 0], a[mi], b[nb][0], b[nb][2]);
                MMA16816(acc[mi][nb * 2 + 1], a[mi], b[nb][1], b[nb][3]);
            }
    }

    // ---------------- stage raw dots into f32 smem tile (aliases A/B) --------
    __syncthreads();                       // all ldmatrix reads done
    float* st = (float*)(smem + OFF_ST);
    const int g  = lane >> 2;
    const int tc = lane & 3;
#pragma unroll
    for (int mi = 0; mi < 2; mi++)
#pragma unroll
        for (int nf = 0; nf < 4; nf++)
#pragma unroll
            for (int rr = 0; rr < 2; rr++) {
                const int row = wm * 32 + mi * 16 + g + rr * 8;
                const int col = wn * 32 + nf * 8 + tc * 2;
                *(float2*)&st[row * STW + col] =
                    make_float2(acc[mi][nf][rr * 2], acc[mi][nf][rr * 2 + 1]);
            }
    __syncthreads();

    // ---------------- coalesced epilogue: warp owns 8 full rows ---------------
    const float* fnc = (const float*)(smem + OFF_FNC);
    const int c = cc + lane * 4;
    const bool ok = c < NCLS;
    const float4 cn = *(const float4*)((const float*)(smem + OFF_CNC) + lane * 4);

    float lacc = 0.f;
#pragma unroll
    for (int i = 0; i < 8; i++) {
        const int row = wid * 8 + i;
        const int m = bb + row;
        const float4 d = *(const float4*)&st[row * STW + lane * 4];
        const float fn = fnc[row];
        const int lb = get_label(label, m, is64);
        float4 lg;
        lg.x = d.x - fn - cn.x;
        lg.y = d.y - fn - cn.y;
        lg.z = d.z - fn - cn.z;
        lg.w = d.w - fn - cn.w;
        float4 ml = lg;
        if (lb == c + 0) { ml.x = 2.f * lg.x; lacc += lg.x; }
        if (lb == c + 1) { ml.y = 2.f * lg.y; lacc += lg.y; }
        if (lb == c + 2) { ml.z = 2.f * lg.z; lacc += lg.z; }
        if (lb == c + 3) { ml.w = 2.f * lg.w; lacc += lg.w; }
        if (ok) {
            const size_t off = (size_t)m * NCLS + c;
            *(float4*)(logits + off)  = lg;
            *(float4*)(mlogits + off) = ml;
        }
    }

    // ---------------- likelihood: warp reduce -> CTA partial -> last CTA ------
#pragma unroll
    for (int o = 16; o > 0; o >>= 1)
        lacc += __shfl_xor_sync(0xffffffffu, lacc, o);
    float* red = (float*)(smem + OFF_RED);
    if (lane == 0) red[wid] = lacc;
    __syncthreads();

    if (tid == 0) {
        float s = ((red[0] + red[1]) + (red[2] + red[3]))
                + ((red[4] + red[5]) + (red[6] + red[7]));
        const int bid = blockIdx.y * 8 + blockIdx.x;
        g_part[bid] = s;
        __threadfence();
        int t = atomicAdd(&g_ticket, 1);
        if (t == NCTA - 1) {
            __threadfence();
            // fixed-order, fixed-split sum => deterministic
            float a0 = 0.f, a1 = 0.f, a2 = 0.f, a3 = 0.f;
            const float4* p4 = (const float4*)g_part;
#pragma unroll
            for (int i = 0; i < NCTA / 4; i++) {
                float4 v = p4[i];
                a0 += v.x; a1 += v.y; a2 += v.z; a3 += v.w;
            }
            *lik = -((a0 + a1) + (a2 + a3)) * (1.f / (float)BATCH);
            g_ticket = 0;          // reset for next graph replay
        }
    }
}

extern "C" void kernel_launch(void* const* d_in, const int* in_sizes, int n_in,
                              void* d_out, int out_size) {
    const float* feat    = (const float*)d_in[0];
    const void*  label   = d_in[1];
    const float* centers = (const float*)d_in[2];

    float* out     = (float*)d_out;
    float* logits  = out;                              // [B, C]
    float* mlogits = out + (size_t)BATCH * NCLS;       // [B, C]
    float* lik     = out + 2 * (size_t)BATCH * NCLS;   // scalar

    cudaFuncSetAttribute(lgm_mma_kernel,
                         cudaFuncAttributeMaxDynamicSharedMemorySize, SMEM_BYTES);

    dim3 grid(8, 32);   // 256 CTAs of 64x128
    lgm_mma_kernel<<<grid, 256, SMEM_BYTES>>>(feat, label, centers,
                                              logits, mlogits, lik);
}

// round 7
// speedup vs baseline: 1.1199x; 1.1199x over previous
#include <cuda_runtime.h>
#include <cuda_bf16.h>
#include <cstdint>

#define BATCH 2048
#define NCLS  1000
#define DIM   128
#define TM 128
#define TN 128
#define ROWB 272            // bf16 tile row stride: 256B + 16B pad (conflict-free)
#define NCTA 128
#define STW 132             // f32 staging row stride in floats (528B)

// deterministic likelihood partials (one per CTA) + completion ticket
__device__ __align__(16) float g_part[NCTA];
__device__ int g_ticket;

// ---- smem byte offsets ----
#define OFF_A   0                       // A bf16 tile: 128 x 272B = 34816
#define OFF_B   34816                   // B bf16 tile: 128 x 272B = 34816
#define OFF_ST  0                       // f32 dots 128 x 528B = 67584 (aliases A+B)
#define OFF_FNP 69632                   // float[128][4] feat norm partials
#define OFF_CNP 71680                   // float[128][4] center norm partials
#define OFF_FNC 73728                   // float[128] 0.5*||f||^2
#define OFF_CNC 74240                   // float[128] 0.5*||c||^2
#define OFF_RED 74752                   // float[16] warp partials
#define SMEM_BYTES 74816

static __device__ __forceinline__ uint32_t smem_u32(const void* p) {
    uint32_t a;
    asm("{ .reg .u64 t; cvta.to.shared.u64 t, %1; cvt.u32.u64 %0, t; }"
        : "=r"(a) : "l"(p));
    return a;
}

static __device__ __forceinline__ int get_label(const void* lab, int b, int is64) {
    if (is64) return (int)(((const long long*)lab)[b]);
    return ((const int*)lab)[b];
}

static __device__ __forceinline__ uint32_t bf2(float x, float y) {
    __nv_bfloat162 v = __floats2bfloat162_rn(x, y);
    return *(uint32_t*)&v;
}

#define LDSM_X4(d, addr)                                                        \
    asm volatile("ldmatrix.sync.aligned.m8n8.x4.shared.b16 {%0,%1,%2,%3},[%4];" \
        : "=r"((d)[0]), "=r"((d)[1]), "=r"((d)[2]), "=r"((d)[3])                \
        : "r"(addr))

#define MMA16816(d, a, b0, b1)                                                  \
    asm volatile("mma.sync.aligned.m16n8k16.row.col.f32.bf16.bf16.f32 "         \
        "{%0,%1,%2,%3}, {%4,%5,%6,%7}, {%8,%9}, {%0,%1,%2,%3};"                 \
        : "+f"((d)[0]), "+f"((d)[1]), "+f"((d)[2]), "+f"((d)[3])                \
        : "r"((a)[0]), "r"((a)[1]), "r"((a)[2]), "r"((a)[3]),                   \
          "r"(b0), "r"(b1))

__global__ void __launch_bounds__(512, 1)
lgm_mma_kernel(const float* __restrict__ feat,
               const void*  __restrict__ label,
               const float* __restrict__ centers,
               float* __restrict__ logits,
               float* __restrict__ mlogits,
               float* __restrict__ lik)
{
    extern __shared__ char smem[];
    const uint32_t sb = smem_u32(smem);
    const int tid = threadIdx.x;
    const int bb = blockIdx.y * TM;      // feat-row base
    const int cc = blockIdx.x * TN;      // center-col base

    // ------------- staging: f32 -> bf16 tiles + fused norms (512 thr) --------
    // thread -> (row = tid&127, 32-col quarter = tid>>7): 8 LDG.128, 4 STS.128
    const int r = tid & 127;
    const int q = tid >> 7;
    {   // A = feat (always in-bounds)
        const float4* src = (const float4*)(feat + (size_t)(bb + r) * DIM + q * 32);
        float4 v[8];
#pragma unroll
        for (int j = 0; j < 8; j++) v[j] = src[j];
        float s = 0.f;
        char* dst = smem + OFF_A + r * ROWB + q * 64;
#pragma unroll
        for (int j = 0; j < 4; j++) {
            float4 a = v[2 * j], b = v[2 * j + 1];
            s += a.x*a.x + a.y*a.y + a.z*a.z + a.w*a.w
               + b.x*b.x + b.y*b.y + b.z*b.z + b.w*b.w;
            uint4 p;
            p.x = bf2(a.x, a.y); p.y = bf2(a.z, a.w);
            p.z = bf2(b.x, b.y); p.w = bf2(b.z, b.w);
            *(uint4*)(dst + j * 16) = p;
        }
        ((float*)(smem + OFF_FNP))[r * 4 + q] = s;
    }
    {   // B = centers (zero-fill rows >= NCLS)
        const int crow = cc + r;
        const bool ok = crow < NCLS;
        const float4* src = (const float4*)(centers + (size_t)crow * DIM + q * 32);
        float4 v[8];
#pragma unroll
        for (int j = 0; j < 8; j++)
            v[j] = ok ? src[j] : make_float4(0.f, 0.f, 0.f, 0.f);
        float s = 0.f;
        char* dst = smem + OFF_B + r * ROWB + q * 64;
#pragma unroll
        for (int j = 0; j < 4; j++) {
            float4 a = v[2 * j], b = v[2 * j + 1];
            s += a.x*a.x + a.y*a.y + a.z*a.z + a.w*a.w
               + b.x*b.x + b.y*b.y + b.z*b.z + b.w*b.w;
            uint4 p;
            p.x = bf2(a.x, a.y); p.y = bf2(a.z, a.w);
            p.z = bf2(b.x, b.y); p.w = bf2(b.z, b.w);
            *(uint4*)(dst + j * 16) = p;
        }
        ((float*)(smem + OFF_CNP))[r * 4 + q] = s;
    }

    // label dtype probe (global rows 0..127, in-bounds for both widths)
    int hw = 0;
    if (tid < 128) hw = (((const int*)label)[2 * tid + 1] != 0);
    const int is64 = !__syncthreads_or(hw);   // barrier also covers tile stores

    if (tid < 128) {
        const float* fnp = (const float*)(smem + OFF_FNP) + tid * 4;
        const float* cnp = (const float*)(smem + OFF_CNP) + tid * 4;
        ((float*)(smem + OFF_FNC))[tid] =
            0.5f * ((fnp[0] + fnp[1]) + (fnp[2] + fnp[3]));
        ((float*)(smem + OFF_CNC))[tid] =
            0.5f * ((cnp[0] + cnp[1]) + (cnp[2] + cnp[3]));
    }
    __syncthreads();

    // ------------- HMMA mainloop: 16 warps, warp = 32(M) x 32(N) -------------
    const int wid  = tid >> 5;
    const int lane = tid & 31;
    const int wm = wid & 3;          // rows wm*32..+31
    const int wn = wid >> 2;         // cols wn*32..+31

    const uint32_t la  = sb + OFF_A + (wm * 32 + (lane & 15)) * ROWB + (lane >> 4) * 16;
    const uint32_t lbm = sb + OFF_B + (wn * 32 + (lane & 15)) * ROWB + (lane >> 4) * 16;

    float acc[2][4][4] = {};
    uint32_t a[2][2][4], b[2][2][4];      // [buf][half][frag]
    LDSM_X4(a[0][0], la);
    LDSM_X4(a[0][1], la + 16 * ROWB);
    LDSM_X4(b[0][0], lbm);
    LDSM_X4(b[0][1], lbm + 16 * ROWB);
#pragma unroll
    for (int ks = 0; ks < 8; ks++) {
        const int cur = ks & 1, nxt = cur ^ 1;
        if (ks < 7) {
            const uint32_t ko = (ks + 1) * 32;
            LDSM_X4(a[nxt][0], la + ko);
            LDSM_X4(a[nxt][1], la + 16 * ROWB + ko);
            LDSM_X4(b[nxt][0], lbm + ko);
            LDSM_X4(b[nxt][1], lbm + 16 * ROWB + ko);
        }
#pragma unroll
        for (int mi = 0; mi < 2; mi++)
#pragma unroll
            for (int nb = 0; nb < 2; nb++) {
                MMA16816(acc[mi][nb * 2 + 0], a[cur][mi], b[cur][nb][0], b[cur][nb][2]);
                MMA16816(acc[mi][nb * 2 + 1], a[cur][mi], b[cur][nb][1], b[cur][nb][3]);
            }
    }

    // ------------- stage raw dots into f32 smem tile (aliases A/B) -----------
    __syncthreads();                       // all ldmatrix reads done
    float* st = (float*)(smem + OFF_ST);
    const int g  = lane >> 2;
    const int tc = lane & 3;
#pragma unroll
    for (int mi = 0; mi < 2; mi++)
#pragma unroll
        for (int nf = 0; nf < 4; nf++)
#pragma unroll
            for (int rr = 0; rr < 2; rr++) {
                const int row = wm * 32 + mi * 16 + g + rr * 8;
                const int col = wn * 32 + nf * 8 + tc * 2;
                *(float2*)&st[row * STW + col] =
                    make_float2(acc[mi][nf][rr * 2], acc[mi][nf][rr * 2 + 1]);
            }
    __syncthreads();

    // ------------- coalesced epilogue: warp owns 8 full rows ------------------
    const float* fnc = (const float*)(smem + OFF_FNC);
    const int c = cc + lane * 4;
    const bool ok = c < NCLS;
    const float4 cn = *(const float4*)((const float*)(smem + OFF_CNC) + lane * 4);

    float lacc = 0.f;
#pragma unroll
    for (int i = 0; i < 8; i++) {
        const int row = wid * 8 + i;
        const int m = bb + row;
        const float4 d = *(const float4*)&st[row * STW + lane * 4];
        const float fn = fnc[row];
        const int lb = get_label(label, m, is64);
        float4 lg;
        lg.x = d.x - fn - cn.x;
        lg.y = d.y - fn - cn.y;
        lg.z = d.z - fn - cn.z;
        lg.w = d.w - fn - cn.w;
        float4 ml = lg;
        if (lb == c + 0) { ml.x = 2.f * lg.x; lacc += lg.x; }
        if (lb == c + 1) { ml.y = 2.f * lg.y; lacc += lg.y; }
        if (lb == c + 2) { ml.z = 2.f * lg.z; lacc += lg.z; }
        if (lb == c + 3) { ml.w = 2.f * lg.w; lacc += lg.w; }
        if (ok) {
            const size_t off = (size_t)m * NCLS + c;
            *(float4*)(logits + off)  = lg;
            *(float4*)(mlogits + off) = ml;
        }
    }

    // ------------- likelihood: warp reduce -> CTA partial -> last CTA ---------
#pragma unroll
    for (int o = 16; o > 0; o >>= 1)
        lacc += __shfl_xor_sync(0xffffffffu, lacc, o);
    float* red = (float*)(smem + OFF_RED);
    if (lane == 0) red[wid] = lacc;
    __syncthreads();

    if (tid == 0) {
        float s = (((red[0] + red[1]) + (red[2] + red[3]))
                 + ((red[4] + red[5]) + (red[6] + red[7])))
                + (((red[8] + red[9]) + (red[10] + red[11]))
                 + ((red[12] + red[13]) + (red[14] + red[15])));
        const int bid = blockIdx.y * 8 + blockIdx.x;
        g_part[bid] = s;
        __threadfence();
        int t = atomicAdd(&g_ticket, 1);
        if (t == NCTA - 1) {
            __threadfence();
            // fixed-order, fixed-split sum => deterministic
            float a0 = 0.f, a1 = 0.f, a2 = 0.f, a3 = 0.f;
            const float4* p4 = (const float4*)g_part;
#pragma unroll
            for (int i = 0; i < NCTA / 4; i++) {
                float4 v = p4[i];
                a0 += v.x; a1 += v.y; a2 += v.z; a3 += v.w;
            }
            *lik = -((a0 + a1) + (a2 + a3)) * (1.f / (float)BATCH);
            g_ticket = 0;          // reset for next graph replay
        }
    }
}

extern "C" void kernel_launch(void* const* d_in, const int* in_sizes, int n_in,
                              void* d_out, int out_size) {
    const float* feat    = (const float*)d_in[0];
    const void*  label   = d_in[1];
    const float* centers = (const float*)d_in[2];

    float* out     = (float*)d_out;
    float* logits  = out;                              // [B, C]
    float* mlogits = out + (size_t)BATCH * NCLS;       // [B, C]
    float* lik     = out + 2 * (size_t)BATCH * NCLS;   // scalar

    cudaFuncSetAttribute(lgm_mma_kernel,
                         cudaFuncAttributeMaxDynamicSharedMemorySize, SMEM_BYTES);

    dim3 grid(8, 16);   // 128 CTAs of 128x128, one per SM
    lgm_mma_kernel<<<grid, 512, SMEM_BYTES>>>(feat, label, centers,
                                              logits, mlogits, lik);
}

// round 8
// speedup vs baseline: 1.1478x; 1.0250x over previous
#include <cuda_runtime.h>
#include <cuda_bf16.h>
#include <cstdint>

#define BATCH 2048
#define NCLS  1000
#define DIM   128
#define TM 128
#define TN 128
#define ROWB 272            // bf16 tile row stride: 256B + 16B pad (conflict-free)
#define NCTA 128
#define STW 132             // f32 staging row stride in floats (528B)

// deterministic likelihood partials (one per CTA) + completion ticket
__device__ __align__(16) float g_part[NCTA];
__device__ int g_ticket;

// ---- smem byte offsets ----
#define OFF_A   0                       // A bf16 tile: 128 x 272B = 34816
#define OFF_B   34816                   // B bf16 tile: 128 x 272B = 34816
#define OFF_ST  0                       // f32 dots 128 x 528B = 67584 (aliases A+B)
#define OFF_FNP 69632                   // float[128][4] feat norm partials
#define OFF_CNP 71680                   // float[128][4] center norm partials
#define OFF_FNC 73728                   // float[128] 0.5*||f||^2
#define OFF_CNC 74240                   // float[128] 0.5*||c||^2
#define OFF_RED 74752                   // float[16] warp partials
#define SMEM_BYTES 74816

static __device__ __forceinline__ uint32_t smem_u32(const void* p) {
    uint32_t a;
    asm("{ .reg .u64 t; cvta.to.shared.u64 t, %1; cvt.u32.u64 %0, t; }"
        : "=r"(a) : "l"(p));
    return a;
}

static __device__ __forceinline__ int get_label(const void* lab, int b, int is64) {
    if (is64) return (int)(((const long long*)lab)[b]);
    return ((const int*)lab)[b];
}

static __device__ __forceinline__ uint32_t bf2(float x, float y) {
    __nv_bfloat162 v = __floats2bfloat162_rn(x, y);
    return *(uint32_t*)&v;
}

#define LDSM_X4(d, addr)                                                        \
    asm volatile("ldmatrix.sync.aligned.m8n8.x4.shared.b16 {%0,%1,%2,%3},[%4];" \
        : "=r"((d)[0]), "=r"((d)[1]), "=r"((d)[2]), "=r"((d)[3])                \
        : "r"(addr))

#define MMA16816(d, a, b0, b1)                                                  \
    asm volatile("mma.sync.aligned.m16n8k16.row.col.f32.bf16.bf16.f32 "         \
        "{%0,%1,%2,%3}, {%4,%5,%6,%7}, {%8,%9}, {%0,%1,%2,%3};"                 \
        : "+f"((d)[0]), "+f"((d)[1]), "+f"((d)[2]), "+f"((d)[3])                \
        : "r"((a)[0]), "r"((a)[1]), "r"((a)[2]), "r"((a)[3]),                   \
          "r"(b0), "r"(b1))

__global__ void __launch_bounds__(512, 1)
lgm_mma_kernel(const float* __restrict__ feat,
               const void*  __restrict__ label,
               const float* __restrict__ centers,
               float* __restrict__ logits,
               float* __restrict__ mlogits,
               float* __restrict__ lik)
{
    extern __shared__ char smem[];
    const uint32_t sb = smem_u32(smem);
    const int tid = threadIdx.x;
    const int bb = blockIdx.y * TM;      // feat-row base
    const int cc = blockIdx.x * TN;      // center-col base

    // ------------- staging: f32 -> bf16 tiles + fused norms (512 thr) --------
    // thread -> (row = tid&127, 32-col quarter = tid>>7): 8 LDG.128, 4 STS.128
    const int r = tid & 127;
    const int q = tid >> 7;
    {   // A = feat (always in-bounds)
        const float4* src = (const float4*)(feat + (size_t)(bb + r) * DIM + q * 32);
        float4 v[8];
#pragma unroll
        for (int j = 0; j < 8; j++) v[j] = src[j];
        float s = 0.f;
        char* dst = smem + OFF_A + r * ROWB + q * 64;
#pragma unroll
        for (int j = 0; j < 4; j++) {
            float4 a = v[2 * j], b = v[2 * j + 1];
            s += a.x*a.x + a.y*a.y + a.z*a.z + a.w*a.w
               + b.x*b.x + b.y*b.y + b.z*b.z + b.w*b.w;
            uint4 p;
            p.x = bf2(a.x, a.y); p.y = bf2(a.z, a.w);
            p.z = bf2(b.x, b.y); p.w = bf2(b.z, b.w);
            *(uint4*)(dst + j * 16) = p;
        }
        ((float*)(smem + OFF_FNP))[r * 4 + q] = s;
    }
    {   // B = centers (zero-fill rows >= NCLS)
        const int crow = cc + r;
        const bool ok = crow < NCLS;
        const float4* src = (const float4*)(centers + (size_t)crow * DIM + q * 32);
        float4 v[8];
#pragma unroll
        for (int j = 0; j < 8; j++)
            v[j] = ok ? src[j] : make_float4(0.f, 0.f, 0.f, 0.f);
        float s = 0.f;
        char* dst = smem + OFF_B + r * ROWB + q * 64;
#pragma unroll
        for (int j = 0; j < 4; j++) {
            float4 a = v[2 * j], b = v[2 * j + 1];
            s += a.x*a.x + a.y*a.y + a.z*a.z + a.w*a.w
               + b.x*b.x + b.y*b.y + b.z*b.z + b.w*b.w;
            uint4 p;
            p.x = bf2(a.x, a.y); p.y = bf2(a.z, a.w);
            p.z = bf2(b.x, b.y); p.w = bf2(b.z, b.w);
            *(uint4*)(dst + j * 16) = p;
        }
        ((float*)(smem + OFF_CNP))[r * 4 + q] = s;
    }

    // label dtype probe (global rows 0..127, in-bounds for both widths)
    int hw = 0;
    if (tid < 128) hw = (((const int*)label)[2 * tid + 1] != 0);
    const int is64 = !__syncthreads_or(hw);   // barrier also covers tile stores

    if (tid < 128) {
        const float* fnp = (const float*)(smem + OFF_FNP) + tid * 4;
        const float* cnp = (const float*)(smem + OFF_CNP) + tid * 4;
        ((float*)(smem + OFF_FNC))[tid] =
            0.5f * ((fnp[0] + fnp[1]) + (fnp[2] + fnp[3]));
        ((float*)(smem + OFF_CNC))[tid] =
            0.5f * ((cnp[0] + cnp[1]) + (cnp[2] + cnp[3]));
    }
    __syncthreads();

    // ------------- HMMA mainloop: 16 warps, warp = 32(M) x 32(N) -------------
    const int wid  = tid >> 5;
    const int lane = tid & 31;
    const int wm = wid & 3;          // rows wm*32..+31
    const int wn = wid >> 2;         // cols wn*32..+31

    const uint32_t la  = sb + OFF_A + (wm * 32 + (lane & 15)) * ROWB + (lane >> 4) * 16;
    const uint32_t lbm = sb + OFF_B + (wn * 32 + (lane & 15)) * ROWB + (lane >> 4) * 16;

    float acc[2][4][4] = {};
    uint32_t a[2][2][4], b[2][2][4];      // [buf][half][frag]
    LDSM_X4(a[0][0], la);
    LDSM_X4(a[0][1], la + 16 * ROWB);
    LDSM_X4(b[0][0], lbm);
    LDSM_X4(b[0][1], lbm + 16 * ROWB);
#pragma unroll
    for (int ks = 0; ks < 8; ks++) {
        const int cur = ks & 1, nxt = cur ^ 1;
        if (ks < 7) {
            const uint32_t ko = (ks + 1) * 32;
            LDSM_X4(a[nxt][0], la + ko);
            LDSM_X4(a[nxt][1], la + 16 * ROWB + ko);
            LDSM_X4(b[nxt][0], lbm + ko);
            LDSM_X4(b[nxt][1], lbm + 16 * ROWB + ko);
        }
#pragma unroll
        for (int mi = 0; mi < 2; mi++)
#pragma unroll
            for (int nb = 0; nb < 2; nb++) {
                MMA16816(acc[mi][nb * 2 + 0], a[cur][mi], b[cur][nb][0], b[cur][nb][2]);
                MMA16816(acc[mi][nb * 2 + 1], a[cur][mi], b[cur][nb][1], b[cur][nb][3]);
            }
    }

    // ------------- stage raw dots into f32 smem tile (aliases A/B) -----------
    __syncthreads();                       // all ldmatrix reads done
    float* st = (float*)(smem + OFF_ST);
    const int g  = lane >> 2;
    const int tc = lane & 3;
#pragma unroll
    for (int mi = 0; mi < 2; mi++)
#pragma unroll
        for (int nf = 0; nf < 4; nf++)
#pragma unroll
            for (int rr = 0; rr < 2; rr++) {
                const int row = wm * 32 + mi * 16 + g + rr * 8;
                const int col = wn * 32 + nf * 8 + tc * 2;
                *(float2*)&st[row * STW + col] =
                    make_float2(acc[mi][nf][rr * 2], acc[mi][nf][rr * 2 + 1]);
            }
    __syncthreads();

    // ------------- coalesced epilogue: warp owns 8 full rows ------------------
    const float* fnc = (const float*)(smem + OFF_FNC);
    const int c = cc + lane * 4;
    const bool ok = c < NCLS;
    const float4 cn = *(const float4*)((const float*)(smem + OFF_CNC) + lane * 4);

    float lacc = 0.f;
#pragma unroll
    for (int i = 0; i < 8; i++) {
        const int row = wid * 8 + i;
        const int m = bb + row;
        const float4 d = *(const float4*)&st[row * STW + lane * 4];
        const float fn = fnc[row];
        const int lb = get_label(label, m, is64);
        float4 lg;
        lg.x = d.x - fn - cn.x;
        lg.y = d.y - fn - cn.y;
        lg.z = d.z - fn - cn.z;
        lg.w = d.w - fn - cn.w;
        float4 ml = lg;
        if (lb == c + 0) { ml.x = 2.f * lg.x; lacc += lg.x; }
        if (lb == c + 1) { ml.y = 2.f * lg.y; lacc += lg.y; }
        if (lb == c + 2) { ml.z = 2.f * lg.z; lacc += lg.z; }
        if (lb == c + 3) { ml.w = 2.f * lg.w; lacc += lg.w; }
        if (ok) {
            const size_t off = (size_t)m * NCLS + c;
            *(float4*)(logits + off)  = lg;
            *(float4*)(mlogits + off) = ml;
        }
    }

    // ------------- likelihood: warp reduce -> CTA partial -> last CTA ---------
#pragma unroll
    for (int o = 16; o > 0; o >>= 1)
        lacc += __shfl_xor_sync(0xffffffffu, lacc, o);
    float* red = (float*)(smem + OFF_RED);
    if (lane == 0) red[wid] = lacc;
    __syncthreads();

    if (tid == 0) {
        float s = (((red[0] + red[1]) + (red[2] + red[3]))
                 + ((red[4] + red[5]) + (red[6] + red[7])))
                + (((red[8] + red[9]) + (red[10] + red[11]))
                 + ((red[12] + red[13]) + (red[14] + red[15])));
        const int bid = blockIdx.y * 8 + blockIdx.x;
        g_part[bid] = s;
        __threadfence();
        int t = atomicAdd(&g_ticket, 1);
        if (t == NCTA - 1) {
            __threadfence();
            // fixed-order, fixed-split sum => deterministic
            float a0 = 0.f, a1 = 0.f, a2 = 0.f, a3 = 0.f;
            const float4* p4 = (const float4*)g_part;
#pragma unroll
            for (int i = 0; i < NCTA / 4; i++) {
                float4 v = p4[i];
                a0 += v.x; a1 += v.y; a2 += v.z; a3 += v.w;
            }
            *lik = -((a0 + a1) + (a2 + a3)) * (1.f / (float)BATCH);
            g_ticket = 0;          // reset for next graph replay
        }
    }
}

extern "C" void kernel_launch(void* const* d_in, const int* in_sizes, int n_in,
                              void* d_out, int out_size) {
    const float* feat    = (const float*)d_in[0];
    const void*  label   = d_in[1];
    const float* centers = (const float*)d_in[2];

    float* out     = (float*)d_out;
    float* logits  = out;                              // [B, C]
    float* mlogits = out + (size_t)BATCH * NCLS;       // [B, C]
    float* lik     = out + 2 * (size_t)BATCH * NCLS;   // scalar

    cudaFuncSetAttribute(lgm_mma_kernel,
                         cudaFuncAttributeMaxDynamicSharedMemorySize, SMEM_BYTES);

    dim3 grid(8, 16);   // 128 CTAs of 128x128, one per SM
    lgm_mma_kernel<<<grid, 512, SMEM_BYTES>>>(feat, label, centers,
                                              logits, mlogits, lik);
}

// round 9
// speedup vs baseline: 1.2944x; 1.1277x over previous
#include <cuda_runtime.h>
#include <cuda_bf16.h>
#include <cstdint>

#define BATCH 2048
#define NCLS  1000
#define CPAD  1024          // centers padded row count
#define DIM   128
#define TM 128
#define TN 128
#define ROWB 272            // bf16 smem row stride: 256B + 16B pad (conflict-free)
#define NCTA 128
#define STW 132             // f32 staging row stride in floats (528B)

// ---- device scratch (allocation-free rule: device globals) ----
__device__ __align__(16) __nv_bfloat16 g_featb[BATCH * DIM];   // 512 KB
__device__ __align__(16) __nv_bfloat16 g_cenb[CPAD * DIM];     // 256 KB
__device__ __align__(16) float g_fn[BATCH];                    // 0.5*||f||^2
__device__ __align__(16) float g_cn[CPAD];                     // 0.5*||c||^2
__device__ int g_is64;
__device__ __align__(16) float g_part[NCTA];
__device__ int g_ticket;

// ---- smem byte offsets (main kernel) ----
#define OFF_A   0                       // A bf16 tile: 128 x 272B = 34816
#define OFF_B   34816                   // B bf16 tile: 128 x 272B = 34816
#define OFF_ST  0                       // f32 dots 128 x 528B = 67584 (aliases A+B)
#define OFF_RED 69632                   // float[16] warp partials
#define SMEM_BYTES 69696

static __device__ __forceinline__ uint32_t smem_u32(const void* p) {
    uint32_t a;
    asm("{ .reg .u64 t; cvta.to.shared.u64 t, %1; cvt.u32.u64 %0, t; }"
        : "=r"(a) : "l"(p));
    return a;
}

static __device__ __forceinline__ int get_label(const void* lab, int b, int is64) {
    if (is64) return (int)(((const long long*)lab)[b]);
    return ((const int*)lab)[b];
}

static __device__ __forceinline__ uint32_t bf2(float x, float y) {
    __nv_bfloat162 v = __floats2bfloat162_rn(x, y);
    return *(uint32_t*)&v;
}

#define LDSM_X4(d, addr)                                                        \
    asm volatile("ldmatrix.sync.aligned.m8n8.x4.shared.b16 {%0,%1,%2,%3},[%4];" \
        : "=r"((d)[0]), "=r"((d)[1]), "=r"((d)[2]), "=r"((d)[3])                \
        : "r"(addr))

#define MMA16816(d, a, b0, b1)                                                  \
    asm volatile("mma.sync.aligned.m16n8k16.row.col.f32.bf16.bf16.f32 "         \
        "{%0,%1,%2,%3}, {%4,%5,%6,%7}, {%8,%9}, {%0,%1,%2,%3};"                 \
        : "+f"((d)[0]), "+f"((d)[1]), "+f"((d)[2]), "+f"((d)[3])                \
        : "r"((a)[0]), "r"((a)[1]), "r"((a)[2]), "r"((a)[3]),                   \
          "r"(b0), "r"(b1))

// ---------------------------------------------------------------------------
// Prepass: convert feat + centers to bf16 ONCE, compute 0.5*row norms,
// probe label dtype. One warp per row; lane holds one float4.
// Rows [0, BATCH) = feat; [BATCH, BATCH+CPAD) = centers (zero-pad >= NCLS).
// ---------------------------------------------------------------------------
__global__ void __launch_bounds__(256)
prepass_kernel(const float* __restrict__ feat,
               const float* __restrict__ centers,
               const void*  __restrict__ label)
{
    // label dtype probe (CTA 0): int64 labels < 1000 => high words all zero
    int hw = 0;
    if (blockIdx.x == 0 && threadIdx.x < 128)
        hw = (((const int*)label)[2 * threadIdx.x + 1] != 0);
    int any = __syncthreads_or(hw);
    if (blockIdx.x == 0 && threadIdx.x == 0) g_is64 = !any;

    const int row  = blockIdx.x * 8 + (threadIdx.x >> 5);
    const int lane = threadIdx.x & 31;

    const float* src;
    __nv_bfloat16* dst;
    float* ndst;
    bool zero = false;
    if (row < BATCH) {
        src = feat + (size_t)row * DIM;
        dst = g_featb + (size_t)row * DIM;
        ndst = g_fn + row;
    } else {
        const int c = row - BATCH;
        zero = (c >= NCLS);
        src = centers + (size_t)c * DIM;
        dst = g_cenb + (size_t)c * DIM;
        ndst = g_cn + c;
    }

    float4 v = zero ? make_float4(0.f, 0.f, 0.f, 0.f)
                    : ((const float4*)src)[lane];
    float s = v.x * v.x + v.y * v.y + v.z * v.z + v.w * v.w;

    uint2 p;
    p.x = bf2(v.x, v.y);
    p.y = bf2(v.z, v.w);
    *(uint2*)(dst + lane * 4) = p;

#pragma unroll
    for (int o = 16; o > 0; o >>= 1) s += __shfl_xor_sync(0xffffffffu, s, o);
    if (lane == 0) *ndst = 0.5f * s;
}

// ---------------------------------------------------------------------------
// Main kernel: 128x128 tile, 16 warps, bf16 tiles staged straight from the
// pre-converted globals (no cvt), coalesced epilogue via smem dot transpose.
// ---------------------------------------------------------------------------
__global__ void __launch_bounds__(512, 1)
lgm_mma_kernel(const void* __restrict__ label,
               float* __restrict__ logits,
               float* __restrict__ mlogits,
               float* __restrict__ lik)
{
    extern __shared__ char smem[];
    const uint32_t sb = smem_u32(smem);
    const int tid = threadIdx.x;
    const int bb = blockIdx.y * TM;      // feat-row base
    const int cc = blockIdx.x * TN;      // center-row base

    const int wid  = tid >> 5;
    const int lane = tid & 31;
    const int is64 = g_is64;

    // ------------- staging: copy bf16 tiles (32 KB each) into smem -----------
    // flat: thread covers 16B at (j*8192 + tid*16); smem row = j*32 + (tid>>4),
    // 16B column chunk = tid & 15. Warp LDG = 512B contiguous (4 lines).
    {
        const char* srcA = (const char*)(g_featb + (size_t)bb * DIM);
        const char* srcB = (const char*)(g_cenb + (size_t)cc * DIM);
        uint4 va[4], vb[4];
#pragma unroll
        for (int j = 0; j < 4; j++) va[j] = *(const uint4*)(srcA + j * 8192 + tid * 16);
#pragma unroll
        for (int j = 0; j < 4; j++) vb[j] = *(const uint4*)(srcB + j * 8192 + tid * 16);
        const uint32_t soff = (tid >> 4) * ROWB + (tid & 15) * 16;
#pragma unroll
        for (int j = 0; j < 4; j++)
            *(uint4*)(smem + OFF_A + j * 32 * ROWB + soff) = va[j];
#pragma unroll
        for (int j = 0; j < 4; j++)
            *(uint4*)(smem + OFF_B + j * 32 * ROWB + soff) = vb[j];
    }

    // preload epilogue operands (latency hides behind barrier + mainloop)
    int   labs[8];
    float fns[8];
    {
        const int rowbase = bb + wid * 8;
#pragma unroll
        for (int i = 0; i < 8; i++) {
            labs[i] = get_label(label, rowbase + i, is64);
            fns[i]  = g_fn[rowbase + i];
        }
    }
    const float4 cn = *(const float4*)(g_cn + cc + lane * 4);

    __syncthreads();

    // ------------- HMMA mainloop: 16 warps, warp = 32(M) x 32(N) -------------
    const int wm = wid & 3;          // rows wm*32..+31
    const int wn = wid >> 2;         // cols wn*32..+31

    const uint32_t la  = sb + OFF_A + (wm * 32 + (lane & 15)) * ROWB + (lane >> 4) * 16;
    const uint32_t lbm = sb + OFF_B + (wn * 32 + (lane & 15)) * ROWB + (lane >> 4) * 16;

    float acc[2][4][4] = {};
    uint32_t a[2][2][4], b[2][2][4];      // [buf][half][frag]
    LDSM_X4(a[0][0], la);
    LDSM_X4(a[0][1], la + 16 * ROWB);
    LDSM_X4(b[0][0], lbm);
    LDSM_X4(b[0][1], lbm + 16 * ROWB);
#pragma unroll
    for (int ks = 0; ks < 8; ks++) {
        const int cur = ks & 1, nxt = cur ^ 1;
        if (ks < 7) {
            const uint32_t ko = (ks + 1) * 32;
            LDSM_X4(a[nxt][0], la + ko);
            LDSM_X4(a[nxt][1], la + 16 * ROWB + ko);
            LDSM_X4(b[nxt][0], lbm + ko);
            LDSM_X4(b[nxt][1], lbm + 16 * ROWB + ko);
        }
#pragma unroll
        for (int mi = 0; mi < 2; mi++)
#pragma unroll
            for (int nb = 0; nb < 2; nb++) {
                MMA16816(acc[mi][nb * 2 + 0], a[cur][mi], b[cur][nb][0], b[cur][nb][2]);
                MMA16816(acc[mi][nb * 2 + 1], a[cur][mi], b[cur][nb][1], b[cur][nb][3]);
            }
    }

    // ------------- stage raw dots into f32 smem tile (aliases A/B) -----------
    __syncthreads();                       // all ldmatrix reads done
    float* st = (float*)(smem + OFF_ST);
    const int g  = lane >> 2;
    const int tc = lane & 3;
#pragma unroll
    for (int mi = 0; mi < 2; mi++)
#pragma unroll
        for (int nf = 0; nf < 4; nf++)
#pragma unroll
            for (int rr = 0; rr < 2; rr++) {
                const int row = wm * 32 + mi * 16 + g + rr * 8;
                const int col = wn * 32 + nf * 8 + tc * 2;
                *(float2*)&st[row * STW + col] =
                    make_float2(acc[mi][nf][rr * 2], acc[mi][nf][rr * 2 + 1]);
            }
    __syncthreads();

    // ------------- coalesced epilogue: warp owns 8 full rows ------------------
    const int c = cc + lane * 4;
    const bool ok = c < NCLS;

    float lacc = 0.f;
#pragma unroll
    for (int i = 0; i < 8; i++) {
        const int row = wid * 8 + i;
        const int m = bb + row;
        const float4 d = *(const float4*)&st[row * STW + lane * 4];
        const float fn = fns[i];
        const int lb = labs[i];
        float4 lg;
        lg.x = d.x - fn - cn.x;
        lg.y = d.y - fn - cn.y;
        lg.z = d.z - fn - cn.z;
        lg.w = d.w - fn - cn.w;
        float4 ml = lg;
        if (lb == c + 0) { ml.x = 2.f * lg.x; lacc += lg.x; }
        if (lb == c + 1) { ml.y = 2.f * lg.y; lacc += lg.y; }
        if (lb == c + 2) { ml.z = 2.f * lg.z; lacc += lg.z; }
        if (lb == c + 3) { ml.w = 2.f * lg.w; lacc += lg.w; }
        if (ok) {
            const size_t off = (size_t)m * NCLS + c;
            *(float4*)(logits + off)  = lg;
            *(float4*)(mlogits + off) = ml;
        }
    }

    // ------------- likelihood: warp reduce -> CTA partial -> last CTA ---------
#pragma unroll
    for (int o = 16; o > 0; o >>= 1)
        lacc += __shfl_xor_sync(0xffffffffu, lacc, o);
    float* red = (float*)(smem + OFF_RED);
    if (lane == 0) red[wid] = lacc;
    __syncthreads();

    if (tid == 0) {
        float s = (((red[0] + red[1]) + (red[2] + red[3]))
                 + ((red[4] + red[5]) + (red[6] + red[7])))
                + (((red[8] + red[9]) + (red[10] + red[11]))
                 + ((red[12] + red[13]) + (red[14] + red[15])));
        const int bid = blockIdx.y * 8 + blockIdx.x;
        g_part[bid] = s;
        __threadfence();
        int t = atomicAdd(&g_ticket, 1);
        if (t == NCTA - 1) {
            __threadfence();
            // fixed-order, fixed-split sum => deterministic
            float a0 = 0.f, a1 = 0.f, a2 = 0.f, a3 = 0.f;
            const float4* p4 = (const float4*)g_part;
#pragma unroll
            for (int i = 0; i < NCTA / 4; i++) {
                float4 v = p4[i];
                a0 += v.x; a1 += v.y; a2 += v.z; a3 += v.w;
            }
            *lik = -((a0 + a1) + (a2 + a3)) * (1.f / (float)BATCH);
            g_ticket = 0;          // reset for next graph replay
        }
    }
}

extern "C" void kernel_launch(void* const* d_in, const int* in_sizes, int n_in,
                              void* d_out, int out_size) {
    const float* feat    = (const float*)d_in[0];
    const void*  label   = d_in[1];
    const float* centers = (const float*)d_in[2];

    float* out     = (float*)d_out;
    float* logits  = out;                              // [B, C]
    float* mlogits = out + (size_t)BATCH * NCLS;       // [B, C]
    float* lik     = out + 2 * (size_t)BATCH * NCLS;   // scalar

    cudaFuncSetAttribute(lgm_mma_kernel,
                         cudaFuncAttributeMaxDynamicSharedMemorySize, SMEM_BYTES);

    // convert once: (2048 + 1024) rows / 8 rows per CTA = 384 CTAs
    prepass_kernel<<<(BATCH + CPAD) / 8, 256>>>(feat, centers, label);

    dim3 grid(8, 16);   // 128 CTAs of 128x128
    lgm_mma_kernel<<<grid, 512, SMEM_BYTES>>>(label, logits, mlogits, lik);
}